// round 17
// baseline (speedup 1.0000x reference)
#include <cuda_runtime.h>
#include <cuda_bf16.h>
#include <math.h>
#include <stdint.h>

#define NUM_BINS     256
#define BITMAP_WORDS 2048
#define BITMAP_W64   1024
#define PAD          16              // one word64 per 128B L2 line
#define GRID         296             // 2 CTAs/SM -> best measured streaming shape (R6)
#define THREADS      512
#define SMEM_BYTES   65536           // 256*256 occupancy byte map
#define R1_PT        4               // round-1: 4 float4-pairs per thread
#define N1_F4        (GRID * THREADS * R1_PT)   // 606208 f4 = 2.42M samples
#define BATCH        6               // round-2 fallback batch

__device__ unsigned long long g_bm[BITMAP_W64 * PAD];   // 128KB, zero at load
__device__ unsigned int g_sync;                         // spin-barrier counter
__device__ unsigned int g_done;                         // ticket counter

// bits = RN(v*255 + 8388608.5f); 8388608.5f rounds to 8388608.0f, so
// bin = round_half_even(v*255) in [0,255] for v in [0,1). byte1 of bits = 0.
#define BIN_MAGIC 8388608.5f

__device__ __forceinline__ unsigned int bin_bits(float v)
{
    return __float_as_uint(fmaf(v, 255.0f, BIN_MAGIC));
}
__device__ __forceinline__ unsigned int pair_addr(float x, float y)
{
    return __byte_perm(bin_bits(x), bin_bits(y), 0x5504);   // binx<<8 | biny
}
__device__ __forceinline__ void mark4(unsigned char* occ, float4 x, float4 y)
{
    occ[pair_addr(x.x, y.x)] = 1;
    occ[pair_addr(x.y, y.y)] = 1;
    occ[pair_addr(x.z, y.z)] = 1;
    occ[pair_addr(x.w, y.w)] = 1;
}

// gather word64 w from smem byte map (bank-conflict-free) and OR to global
__device__ __forceinline__ void pack_word(const unsigned char* occ, int w)
{
    const unsigned int* occ32 = reinterpret_cast<const unsigned int*>(occ);
    unsigned long long word = 0ull;
    #pragma unroll
    for (int k = 0; k < 16; ++k) {
        int k2 = (k + (w >> 1)) & 15;
        unsigned int v = occ32[w * 16 + k2];             // bytes are exactly 0 or 1
        unsigned long long nib = (v | (v >> 7) | (v >> 14) | (v >> 21)) & 0xFu;
        word |= nib << (4 * k2);
    }
    if (word) atomicOr(&g_bm[w * PAD], word);
}

extern "C" __global__ void __launch_bounds__(THREADS, 2)
mi_fused(const float* __restrict__ X, const float* __restrict__ Y, int n,
         float* __restrict__ out)
{
    extern __shared__ unsigned char occ[];   // 65536 bytes
    __shared__ unsigned s_ticket;

    const int t = threadIdx.x;
    const int b = blockIdx.x;
    const int S = GRID * THREADS;            // 151552
    const int n4 = n >> 2;
    const int n4_1 = (N1_F4 < n4) ? N1_F4 : n4;
    const float4* X4 = reinterpret_cast<const float4*>(X);
    const float4* Y4 = reinterpret_cast<const float4*>(Y);
    const int i0 = b * THREADS + t;

    // ---- round-1 loads FIRST (latency hidden behind the smem zero) ----
    float4 x0, x1, x2, x3, y0, y1, y2, y3;
    const bool full4 = (i0 + 3 * S < n4_1);
    if (full4) {
        x0 = X4[i0];          y0 = Y4[i0];
        x1 = X4[i0 + S];      y1 = Y4[i0 + S];
        x2 = X4[i0 + 2 * S];  y2 = Y4[i0 + 2 * S];
        x3 = X4[i0 + 3 * S];  y3 = Y4[i0 + 3 * S];
    }

    // ---- zero shared occupancy map ----
    uint4* occ4 = reinterpret_cast<uint4*>(occ);
    #pragma unroll
    for (int i = t; i < SMEM_BYTES / 16; i += THREADS)
        occ4[i] = make_uint4(0u, 0u, 0u, 0u);
    __syncthreads();

    // ---- round-1 marks ----
    if (full4) {
        mark4(occ, x0, y0); mark4(occ, x1, y1);
        mark4(occ, x2, y2); mark4(occ, x3, y3);
    } else {
        for (int i = i0; i < n4_1; i += S) {
            float4 x = X4[i], y = Y4[i];
            mark4(occ, x, y);
        }
    }
    if (b == 0) {                       // scalar tail (n not multiple of 4)
        int tail = n & 3, base = n - tail;
        if (t < tail)
            occ[pair_addr(X[base + t], Y[base + t])] = 1;
    }
    __syncthreads();

    // ---- pack: two word64 per thread, CTA-staggered line order ----
    #pragma unroll
    for (int w = t; w < BITMAP_W64; w += THREADS)
        pack_word(occ, (w + b * 7) & (BITMAP_W64 - 1));

    // ---- spin barrier: ALL CTAs stay alive for the check ----
    __threadfence();                    // release this CTA's atomicOrs
    __syncthreads();
    if (t == 0) {
        atomicAdd(&g_sync, 1u);
        while (*(volatile unsigned*)&g_sync < (unsigned)GRID)
            __nanosleep(64);
    }
    __syncthreads();

    // ---- saturation check (every CTA; reads precede any reset) ----
    int ok = 1;
    #pragma unroll
    for (int w = t; w < BITMAP_W64; w += THREADS)
        ok &= (int)(__ldcg(&g_bm[w * PAD]) == ~0ull);

    if (__syncthreads_and(ok)) {
        // All 65536 producible bins set -> further marks are no-ops; MI of the
        // uniform occupancy map is closed-form:
        //   h = 1/65536; px = py = 1/256; mi = log(h/(px*py + 1e-10))
        if (t == 0) s_ticket = atomicAdd(&g_done, 1u);
        __syncthreads();
        if (s_ticket == (unsigned)(GRID - 1)) {
            // last arriver: all other CTAs have finished READING -> safe to reset
            #pragma unroll
            for (int w = t; w < BITMAP_W64; w += THREADS)
                g_bm[w * PAD] = 0ull;
            __syncthreads();
            if (t == 0) {
                const double h = 1.0 / 65536.0;
                out[0] = (float)(1.0 - tanh(log(h / (h + 1e-10))));
                g_sync = 0u;
                g_done = 0u;
            }
        }
        return;
    }

    // ============ fallback: grid-wide exact round 2 ============
    {
        int i = n4_1 + i0;
        for (; i + (BATCH - 1) * S < n4; i += BATCH * S) {
            float4 x[BATCH], y[BATCH];
            #pragma unroll
            for (int k = 0; k < BATCH; ++k) x[k] = X4[i + k * S];
            #pragma unroll
            for (int k = 0; k < BATCH; ++k) y[k] = Y4[i + k * S];
            #pragma unroll
            for (int k = 0; k < BATCH; ++k) mark4(occ, x[k], y[k]);
        }
        for (; i < n4; i += S) {
            float4 x = X4[i], y = Y4[i];
            mark4(occ, x, y);
        }
        __syncthreads();
        #pragma unroll
        for (int w = t; w < BITMAP_W64; w += THREADS)
            pack_word(occ, (w + b * 7) & (BITMAP_W64 - 1));
        __threadfence();
        __syncthreads();
    }

    if (t == 0) s_ticket = atomicAdd(&g_done, 1u);
    __syncthreads();
    if (s_ticket != (unsigned)(GRID - 1)) return;
    __threadfence();                    // acquire all CTAs' round-2 ORs

    // full epilogue (last CTA only; all-float MI)
    unsigned int* sbm  = reinterpret_cast<unsigned int*>(occ);          // 8192 B
    int*          rowc = reinterpret_cast<int*>(occ + 8192);            // 1024 B
    float*        pyv  = reinterpret_cast<float*>(occ + 9216);          // 1024 B
    float*        part = reinterpret_cast<float*>(occ + 10240);         // 1024 B
    int*          sN   = reinterpret_cast<int*>(occ + 12288);

    __syncthreads();
    if (t == 0) *sN = 0;
    for (int w64 = t; w64 < BITMAP_W64; w64 += THREADS) {
        unsigned long long v = __ldcg(&g_bm[w64 * PAD]);
        sbm[2 * w64]     = (unsigned int)v;
        sbm[2 * w64 + 1] = (unsigned int)(v >> 32);
        g_bm[w64 * PAD] = 0ull;         // reset for next graph replay
    }
    __syncthreads();

    unsigned int rw[8];
    if (t < NUM_BINS) {                 // thread t = row t
        int rc = 0;
        #pragma unroll
        for (int k = 0; k < 8; ++k) { rw[k] = sbm[t * 8 + k]; rc += __popc(rw[k]); }
        rowc[t] = rc;
        atomicAdd(sN, rc);
    }
    __syncthreads();

    const float invN = 1.0f / (float)(*sN);

    if (t < NUM_BINS) {                 // thread t = column t
        int wo = t >> 5, sh = t & 31;
        int cc = 0;
        #pragma unroll 8
        for (int bx = 0; bx < NUM_BINS; ++bx)
            cc += (sbm[bx * 8 + wo] >> sh) & 1;
        pyv[t] = (float)cc * invN;
    }
    __syncthreads();

    if (t < NUM_BINS) {                 // MI contribution of row t
        float pxf    = (float)rowc[t] * invN;
        float logInv = __logf(invN);
        float acc = 0.0f;
        #pragma unroll 8
        for (int j = 0; j < NUM_BINS; ++j) {
            if ((rw[j >> 5] >> (j & 31)) & 1u) {
                float d = fmaf(pxf, pyv[j], 1e-10f);
                acc += logInv - __logf(d);
            }
        }
        part[t] = acc * invN;
    }
    __syncthreads();

    for (int s = 128; s > 0; s >>= 1) {
        if (t < s) part[t] += part[t + s];
        __syncthreads();
    }
    if (t == 0) {
        out[0] = (float)(1.0 - tanh((double)part[0]));
        g_sync = 0u;
        g_done = 0u;
    }
}

extern "C" void kernel_launch(void* const* d_in, const int* in_sizes, int n_in,
                              void* d_out, int out_size)
{
    const float* X = (const float*)d_in[0];   // I_complementary
    const float* Y = (const float*)d_in[1];   // I_target
    float* out = (float*)d_out;
    int n = in_sizes[0];

    static bool attr_done = false;
    if (!attr_done) {
        cudaFuncSetAttribute(mi_fused, cudaFuncAttributeMaxDynamicSharedMemorySize,
                             SMEM_BYTES);
        attr_done = true;
    }
    mi_fused<<<GRID, THREADS, SMEM_BYTES>>>(X, Y, n, out);
}